// round 11
// baseline (speedup 1.0000x reference)
#include <cuda_runtime.h>
#include <cuda_bf16.h>
#include <math.h>
#include <stdint.h>

#define NROWS 4096
#define DDIM  1024
#define TWO_N 8192

#define BM 128
#define BN 256
#define BK 64                    // int8 elements per stage
#define NKB (DDIM / BK)          // 16 k-blocks
#define ROWB 80                  // 64B data + 16B pad -> conflict-free ldmatrix
#define BOFF (BM * ROWB)         // B tile offset within a stage (10240)
#define STAGE_BYTES ((BM + BN) * ROWB)   // 30720
#define SMEM_TOTAL (3 * STAGE_BYTES)     // 92160

// quantization: store s8 = round(512 * x_normalized); logit = acc * 20 / 512^2
#define QSCALE 512.0f
#define LOGIT_SCALE (20.0f / (QSCALE * QSCALE))

__device__ uint8_t g_x8[NROWS * DDIM];     // normalized input, s8 (x512)
__device__ uint8_t g_cat8[TWO_N * DDIM];   // normalized [target; hard_negative], s8 (x512)
__device__ float g_rowsum[NROWS];
__device__ float g_diag[NROWS];

// ---------------------------------------------------------------------------
__device__ __forceinline__ uint32_t smem_u32(const void* p) {
    uint32_t a;
    asm("{ .reg .u64 t; cvta.to.shared.u64 t, %1; cvt.u32.u64 %0, t; }" : "=r"(a) : "l"(p));
    return a;
}
__device__ __forceinline__ void cp16(uint32_t dst, const void* src) {
    asm volatile("cp.async.cg.shared.global [%0], [%1], 16;" :: "r"(dst), "l"(src));
}
__device__ __forceinline__ void ldsm4(uint32_t* r, uint32_t addr) {
    asm volatile("ldmatrix.sync.aligned.m8n8.x4.shared.b16 {%0,%1,%2,%3}, [%4];"
                 : "=r"(r[0]), "=r"(r[1]), "=r"(r[2]), "=r"(r[3]) : "r"(addr));
}
__device__ __forceinline__ void mma_s8(int* c, const uint32_t* a, uint32_t b0, uint32_t b1) {
    asm volatile(
        "mma.sync.aligned.m16n8k32.row.col.s32.s8.s8.s32 "
        "{%0,%1,%2,%3}, {%4,%5,%6,%7}, {%8,%9}, {%0,%1,%2,%3};"
        : "+r"(c[0]), "+r"(c[1]), "+r"(c[2]), "+r"(c[3])
        : "r"(a[0]), "r"(a[1]), "r"(a[2]), "r"(a[3]), "r"(b0), "r"(b1));
}

// ---------------------------------------------------------------------------
// Kernel A: row-normalize (fp32 math) -> s8 (scaled x512); zero g_rowsum.
// ---------------------------------------------------------------------------
__global__ void __launch_bounds__(256) normalize_kernel(
    const float* __restrict__ x,
    const float* __restrict__ t,
    const float* __restrict__ h)
{
    int r = blockIdx.x;
    const float* src;
    uint8_t* dst;
    if (r < NROWS) {
        src = x + (size_t)r * DDIM;            dst = g_x8 + (size_t)r * DDIM;
    } else if (r < 2 * NROWS) {
        src = t + (size_t)(r - NROWS) * DDIM;  dst = g_cat8 + (size_t)(r - NROWS) * DDIM;
    } else {
        src = h + (size_t)(r - 2 * NROWS) * DDIM;
        dst = g_cat8 + (size_t)(r - NROWS) * DDIM;   // h -> cat rows N..2N-1
    }

    int tid = threadIdx.x;
    float4 v = reinterpret_cast<const float4*>(src)[tid];
    float ss = v.x * v.x + v.y * v.y + v.z * v.z + v.w * v.w;

    #pragma unroll
    for (int o = 16; o > 0; o >>= 1) ss += __shfl_xor_sync(0xffffffffu, ss, o);
    __shared__ float warp_s[8];
    int lane = tid & 31, w = tid >> 5;
    if (lane == 0) warp_s[w] = ss;
    __syncthreads();
    if (w == 0) {
        float s = (lane < 8) ? warp_s[lane] : 0.0f;
        #pragma unroll
        for (int o = 4; o > 0; o >>= 1) s += __shfl_xor_sync(0xffffffffu, s, o);
        if (lane == 0) warp_s[0] = s;
    }
    __syncthreads();

    float inv = QSCALE / fmaxf(sqrtf(warp_s[0]), 1e-8f);
    int q0 = __float2int_rn(v.x * inv);
    int q1 = __float2int_rn(v.y * inv);
    int q2 = __float2int_rn(v.z * inv);
    int q3 = __float2int_rn(v.w * inv);
    uint32_t packed = (uint32_t)(q0 & 0xff) | ((uint32_t)(q1 & 0xff) << 8)
                    | ((uint32_t)(q2 & 0xff) << 16) | ((uint32_t)(q3 & 0xff) << 24);
    reinterpret_cast<uint32_t*>(dst)[tid] = packed;

    if (r < NROWS && tid == 0) g_rowsum[r] = 0.0f;
}

// ---------------------------------------------------------------------------
// Kernel B: s8 IMMA GEMM (Xq @ Catqᵀ) 128x256 tile + fused exp/rowsum.
// 256 threads = 8 warps (2 x 4); warp tile 64x64; mma m16n8k32 s8; BK=64.
// 3-stage cp.async ring, prefetch distance 2, one __syncthreads per iter.
// grid = (TWO_N/BN, NROWS/BM) = (32, 32)
// ---------------------------------------------------------------------------
__device__ __forceinline__ void load_stage(uint32_t sstage, int bi, int bj, int k0, int tid)
{
    #pragma unroll
    for (int t = 0; t < 6; t++) {
        int idx = tid + t * 256;            // 0..1535
        int r = idx >> 2, c = idx & 3;      // row 0..383, 16B chunk 0..3
        if (r < BM) {
            const void* gp = g_x8 + (size_t)(bi * BM + r) * DDIM + k0 + c * 16;
            cp16(sstage + (uint32_t)(r * ROWB + c * 16), gp);
        } else {
            int r2 = r - BM;
            const void* gp = g_cat8 + (size_t)(bj * BN + r2) * DDIM + k0 + c * 16;
            cp16(sstage + (uint32_t)(BOFF + r2 * ROWB + c * 16), gp);
        }
    }
    asm volatile("cp.async.commit_group;" ::: "memory");
}

__global__ void __launch_bounds__(256, 1) sim_kernel()
{
    extern __shared__ char smem[];
    const uint32_t sb = smem_u32(smem);
    const int tid = threadIdx.x;
    const int lane = tid & 31;
    const int w = tid >> 5;
    const int wm = w >> 2;       // 0..1 -> rows [wm*64, +64)
    const int wn = w & 3;        // 0..3 -> cols [wn*64, +64)
    const int bi = blockIdx.y, bj = blockIdx.x;

    int acc[4][8][4];
    #pragma unroll
    for (int i = 0; i < 4; i++)
        #pragma unroll
        for (int j = 0; j < 8; j++)
            #pragma unroll
            for (int k = 0; k < 4; k++) acc[i][j][k] = 0;

    // per-lane ldmatrix base addresses (b16 view: 1 b16 = 2 s8)
    const uint32_t aBase = sb + (uint32_t)((wm * 64 + (lane & 15)) * ROWB + ((lane >> 4) << 4));
    const uint32_t bBase = sb + (uint32_t)(BOFF
                          + (wn * 64 + (lane & 7) + ((lane >> 4) << 3)) * ROWB
                          + (((lane >> 3) & 1) << 4));

    load_stage(sb + 0 * STAGE_BYTES, bi, bj, 0 * BK, tid);
    load_stage(sb + 1 * STAGE_BYTES, bi, bj, 1 * BK, tid);

    for (int kb = 0; kb < NKB; kb++) {
        // stage kb complete; at most stage kb+1 still in flight
        if (kb < NKB - 1) asm volatile("cp.async.wait_group 1;" ::: "memory");
        else              asm volatile("cp.async.wait_group 0;" ::: "memory");
        __syncthreads();   // stage kb visible; fences iter kb-1 reads of buffer (kb+2)%3

        if (kb + 2 < NKB)
            load_stage(sb + (uint32_t)(((kb + 2) % 3) * STAGE_BYTES), bi, bj, (kb + 2) * BK, tid);

        const uint32_t so = (uint32_t)((kb % 3) * STAGE_BYTES);
        #pragma unroll
        for (int kk = 0; kk < 2; kk++) {        // two k32 steps per BK=64 s8
            uint32_t a[4][4], b[4][4];
            #pragma unroll
            for (int mt = 0; mt < 4; mt++)
                ldsm4(a[mt], aBase + so + (uint32_t)(mt * 16 * ROWB + kk * 32));
            #pragma unroll
            for (int g = 0; g < 4; g++)
                ldsm4(b[g], bBase + so + (uint32_t)(g * 16 * ROWB + kk * 32));
            #pragma unroll
            for (int mt = 0; mt < 4; mt++) {
                #pragma unroll
                for (int nt = 0; nt < 8; nt++) {
                    const uint32_t* bp = &b[nt >> 1][(nt & 1) * 2];
                    mma_s8(acc[mt][nt], a[mt], bp[0], bp[1]);
                }
            }
        }
    }

    // Epilogue: logits, hard-neg diag +1, exp, per-row sums.
    #pragma unroll
    for (int mt = 0; mt < 4; mt++) {
        const int gi0 = bi * BM + wm * 64 + mt * 16 + (lane >> 2);
        const int gi1 = gi0 + 8;
        float rs0 = 0.0f, rs1 = 0.0f;
        #pragma unroll
        for (int nt = 0; nt < 8; nt++) {
            const int gj = bj * BN + wn * 64 + nt * 8 + ((lane & 3) << 1);
            float l0 = (float)acc[mt][nt][0] * LOGIT_SCALE;
            float l1 = (float)acc[mt][nt][1] * LOGIT_SCALE;
            float l2 = (float)acc[mt][nt][2] * LOGIT_SCALE;
            float l3 = (float)acc[mt][nt][3] * LOGIT_SCALE;
            if (gj     == gi0 + NROWS) l0 += 1.0f;
            if (gj + 1 == gi0 + NROWS) l1 += 1.0f;
            if (gj     == gi1 + NROWS) l2 += 1.0f;
            if (gj + 1 == gi1 + NROWS) l3 += 1.0f;
            if (gj     == gi0) g_diag[gi0] = l0;
            if (gj + 1 == gi0) g_diag[gi0] = l1;
            if (gj     == gi1) g_diag[gi1] = l2;
            if (gj + 1 == gi1) g_diag[gi1] = l3;
            rs0 += __expf(l0) + __expf(l1);
            rs1 += __expf(l2) + __expf(l3);
        }
        rs0 += __shfl_xor_sync(0xffffffffu, rs0, 1);
        rs0 += __shfl_xor_sync(0xffffffffu, rs0, 2);
        rs1 += __shfl_xor_sync(0xffffffffu, rs1, 1);
        rs1 += __shfl_xor_sync(0xffffffffu, rs1, 2);
        if ((lane & 3) == 0) {
            atomicAdd(&g_rowsum[gi0], rs0);
            atomicAdd(&g_rowsum[gi1], rs1);
        }
    }
}

// ---------------------------------------------------------------------------
// Kernel C: loss = mean_i( log(rowsum_i) - diag_i )
// ---------------------------------------------------------------------------
__global__ void __launch_bounds__(1024) loss_kernel(float* __restrict__ out)
{
    int tid = threadIdx.x;
    float s = 0.0f;
    for (int i = tid; i < NROWS; i += 1024)
        s += logf(g_rowsum[i]) - g_diag[i];

    #pragma unroll
    for (int o = 16; o > 0; o >>= 1) s += __shfl_xor_sync(0xffffffffu, s, o);
    __shared__ float warp_s[32];
    int lane = tid & 31, w = tid >> 5;
    if (lane == 0) warp_s[w] = s;
    __syncthreads();
    if (w == 0) {
        float v = warp_s[lane];
        #pragma unroll
        for (int o = 16; o > 0; o >>= 1) v += __shfl_xor_sync(0xffffffffu, v, o);
        if (lane == 0) out[0] = v / (float)NROWS;
    }
}

// ---------------------------------------------------------------------------
extern "C" void kernel_launch(void* const* d_in, const int* in_sizes, int n_in,
                              void* d_out, int out_size)
{
    const float* x = (const float*)d_in[0];
    const float* t = (const float*)d_in[1];
    const float* h = (const float*)d_in[2];

    cudaFuncSetAttribute(sim_kernel, cudaFuncAttributeMaxDynamicSharedMemorySize, SMEM_TOTAL);

    normalize_kernel<<<3 * NROWS, 256>>>(x, t, h);

    dim3 grid(TWO_N / BN, NROWS / BM);   // (32, 32)
    sim_kernel<<<grid, 256, SMEM_TOTAL>>>();

    loss_kernel<<<1, 1024>>>((float*)d_out);
}